// round 12
// baseline (speedup 1.0000x reference)
#include <cuda_runtime.h>
#include <cuda_fp16.h>
#include <cstdint>

#define NN 50000
#define EE 800000
#define DD 128
#define NG 64
#define SCAN_CHUNK 1024
#define NCHUNK ((NN + SCAN_CHUNK - 1) / SCAN_CHUNK)   // 49

// -------- scratch (device globals: no allocation allowed) --------
__device__ __align__(16) __half g_tmph[NN * DD]; // h @ W result (fp16)
__device__ __align__(16) float g_h[NN * DD];     // aggregated layer output (fp32)
__device__ __align__(16) float g_dinv[NN];       // rsqrt(degree)
__device__ __align__(16) float g_cnt[NG];        // pool counts
__device__ __align__(16) int   g_degi[NN];       // int in-degree (no self loop)
__device__ __align__(16) int   g_rowptr[NN + 1]; // CSR row pointers (by dst)
__device__ __align__(16) int   g_cursor[NN];     // scatter cursors
__device__ __align__(16) int2  g_csr[EE];        // {src, norm-as-int}
__device__ __align__(16) int   g_bsum[NCHUNK];   // per-chunk totals (from scan1)

// ================= prep =================
__global__ void k_zero(float* __restrict__ out) {
    int i = blockIdx.x * blockDim.x + threadIdx.x;
    if (i < NN) g_degi[i] = 0;
    if (i < NG * DD) out[i] = 0.f;
}

__global__ void k_deg_count(const int* __restrict__ ei) {
    int e = blockIdx.x * blockDim.x + threadIdx.x;
    if (e < EE) atomicAdd(&g_degi[ei[EE + e]], 1);
}

// ---- scan phase 1 ----
__global__ void k_scan1() {
    __shared__ int wsum[32];
    int tid = threadIdx.x, lane = tid & 31, wd = tid >> 5;
    int i = blockIdx.x * SCAN_CHUNK + tid;
    int v = (i < NN) ? g_degi[i] : 0;
    int x = v;
#pragma unroll
    for (int o = 1; o < 32; o <<= 1) {
        int y = __shfl_up_sync(0xffffffffu, x, o);
        if (lane >= o) x += y;
    }
    if (lane == 31) wsum[wd] = x;
    __syncthreads();
    if (wd == 0) {
        int s = wsum[lane];
#pragma unroll
        for (int o = 1; o < 32; o <<= 1) {
            int y = __shfl_up_sync(0xffffffffu, s, o);
            if (lane >= o) s += y;
        }
        wsum[lane] = s;
    }
    __syncthreads();
    int excl = (wd ? wsum[wd - 1] : 0) + x - v;
    if (i < NN) g_rowptr[i] = excl;
    if (tid == SCAN_CHUNK - 1) g_bsum[blockIdx.x] = wsum[31];
}

// ---- scan phase 2+3 fused + pool counts (sorted batch) ----
__global__ void k_scan3(const int* __restrict__ batch) {
    __shared__ int pref[NCHUNK];
    int tid = threadIdx.x;
    if (tid == 0) {
        int run = 0;
#pragma unroll 1
        for (int j = 0; j < NCHUNK; j++) {
            int t = g_bsum[j];
            pref[j] = run;
            run += t;
        }
    }
    __syncthreads();
    int i = blockIdx.x * blockDim.x + tid;
    if (i < NN) {
        int rp = g_rowptr[i] + pref[i / SCAN_CHUNK];
        g_rowptr[i] = rp;
        g_cursor[i] = rp;
        g_dinv[i] = rsqrtf((float)(g_degi[i] + 1));
    }
    if (i == 0) g_rowptr[NN] = EE;
    if (blockIdx.x == 0 && tid < NG) {
        int g = tid;
        int lo = 0, hi = NN;
        while (lo < hi) { int m = (lo + hi) >> 1; if (batch[m] < g) lo = m + 1; else hi = m; }
        int start = lo;
        lo = 0; hi = NN;
        while (lo < hi) { int m = (lo + hi) >> 1; if (batch[m] <= g) lo = m + 1; else hi = m; }
        g_cnt[g] = (float)(lo - start);
    }
}

// ---- CSR fill: one 8B write per edge ----
__global__ void k_csr_fill(const int* __restrict__ ei) {
    int e = blockIdx.x * blockDim.x + threadIdx.x;
    if (e < EE) {
        int s = ei[e];
        int d = ei[EE + e];
        int pos = atomicAdd(&g_cursor[d], 1);
        float nm = g_dinv[s] * g_dinv[d];
        g_csr[pos] = make_int2(s, __float_as_int(nm));
    }
}

// ================= GEMM: C_half[M,128] = reluOpt(A)[M,128] @ W[128,128] =================
__global__ __launch_bounds__(128, 4)
void k_gemm(const float* __restrict__ A, const float* __restrict__ W,
            __half* __restrict__ C, int M, int relu_in) {
    __shared__ float As[2][16][68];
    __shared__ float Ws[2][16][128];

    int tid = threadIdx.x;
    int tx = tid & 15;
    int ty = tid >> 4;
    int row0 = blockIdx.x * 64;

    unsigned long long acc[8][4];
#pragma unroll
    for (int i = 0; i < 8; i++)
#pragma unroll
        for (int j = 0; j < 4; j++) acc[i][j] = 0ull;

    float4 aR[2];
    float4 wR[4];

    auto loadT = [&](int kt) {
#pragma unroll
        for (int q = 0; q < 2; q++) {
            int id = tid + q * 128;
            int r = id >> 2;
            int kc = (id & 3) * 4;
            int grow = row0 + r;
            float4 v = make_float4(0.f, 0.f, 0.f, 0.f);
            if (grow < M) v = *(const float4*)&A[(size_t)grow * DD + kt * 16 + kc];
            if (relu_in) {
                v.x = fmaxf(v.x, 0.f); v.y = fmaxf(v.y, 0.f);
                v.z = fmaxf(v.z, 0.f); v.w = fmaxf(v.w, 0.f);
            }
            aR[q] = v;
        }
#pragma unroll
        for (int q = 0; q < 4; q++) {
            int id = tid + q * 128;
            wR[q] = ((const float4*)&W[kt * 16 * DD])[id];
        }
    };
    auto stsT = [&](int b) {
#pragma unroll
        for (int q = 0; q < 2; q++) {
            int id = tid + q * 128;
            int r = id >> 2;
            int kc = (id & 3) * 4;
            As[b][kc + 0][r] = aR[q].x;
            As[b][kc + 1][r] = aR[q].y;
            As[b][kc + 2][r] = aR[q].z;
            As[b][kc + 3][r] = aR[q].w;
        }
#pragma unroll
        for (int q = 0; q < 4; q++) {
            int id = tid + q * 128;
            ((float4*)Ws[b])[id] = wR[q];
        }
    };

    loadT(0);
    stsT(0);
    __syncthreads();

    for (int kt = 0; kt < 8; kt++) {
        if (kt < 7) loadT(kt + 1);
        int b = kt & 1;
#pragma unroll
        for (int k = 0; k < 16; k++) {
            float4 a0 = *(float4*)&As[b][k][ty * 8];
            float4 a1 = *(float4*)&As[b][k][ty * 8 + 4];
            ulonglong2 w0 = *(ulonglong2*)&Ws[b][k][tx * 8];
            ulonglong2 w1 = *(ulonglong2*)&Ws[b][k][tx * 8 + 4];
            unsigned long long wp[4] = {w0.x, w0.y, w1.x, w1.y};
            float av[8] = {a0.x, a0.y, a0.z, a0.w, a1.x, a1.y, a1.z, a1.w};
#pragma unroll
            for (int i = 0; i < 8; i++) {
                unsigned long long ap;
                asm("mov.b64 %0, {%1, %1};" : "=l"(ap) : "r"(__float_as_uint(av[i])));
#pragma unroll
                for (int j = 0; j < 4; j++) {
                    asm("fma.rn.f32x2 %0, %1, %2, %0;"
                        : "+l"(acc[i][j]) : "l"(ap), "l"(wp[j]));
                }
            }
        }
        if (kt < 7) {
            stsT((kt + 1) & 1);
            __syncthreads();
        }
    }

#pragma unroll
    for (int i = 0; i < 8; i++) {
        int grow = row0 + ty * 8 + i;
        if (grow < M) {
            __half2 hv[4];
#pragma unroll
            for (int j = 0; j < 4; j++) {
                unsigned int lo, hi;
                asm("mov.b64 {%0, %1}, %2;" : "=r"(lo), "=r"(hi) : "l"(acc[i][j]));
                hv[j] = __floats2half2_rn(__uint_as_float(lo), __uint_as_float(hi));
            }
            *(uint4*)&C[(size_t)grow * DD + tx * 8] =
                make_uint4(*(unsigned*)&hv[0], *(unsigned*)&hv[1],
                           *(unsigned*)&hv[2], *(unsigned*)&hv[3]);
        }
    }
}

// ================= gather aggregation: one warp per dst node (fp16 gathers) =================
__device__ __forceinline__ void acc_half4(float4& acc, uint2 raw, float nm) {
    __half2 p0 = *(__half2*)&raw.x;
    __half2 p1 = *(__half2*)&raw.y;
    float2 f0 = __half22float2(p0);
    float2 f1 = __half22float2(p1);
    acc.x = fmaf(f0.x, nm, acc.x);
    acc.y = fmaf(f0.y, nm, acc.y);
    acc.z = fmaf(f1.x, nm, acc.z);
    acc.w = fmaf(f1.y, nm, acc.w);
}

template <int FINAL>
__global__ void k_agg(const float* __restrict__ b,
                      const int* __restrict__ batch,
                      float* __restrict__ out) {
    int warp = (blockIdx.x * blockDim.x + threadIdx.x) >> 5;
    int lane = threadIdx.x & 31;
    if (warp >= NN) return;
    int d = warp;

    const uint2* tp = (const uint2*)g_tmph;   // 8B = 4 halfs per lane-slot

    float di = g_dinv[d];
    float n2 = di * di;
    float4 bb = ((const float4*)b)[lane];
    float4 acc = bb;
    acc_half4(acc, tp[d * 32 + lane], n2);

    int idx = g_rowptr[d];
    int end = g_rowptr[d + 1];
    for (; idx + 1 < end; idx += 2) {
        int2 c0 = g_csr[idx];
        int2 c1 = g_csr[idx + 1];
        uint2 r0 = tp[c0.x * 32 + lane];
        uint2 r1 = tp[c1.x * 32 + lane];
        acc_half4(acc, r0, __int_as_float(c0.y));
        acc_half4(acc, r1, __int_as_float(c1.y));
    }
    if (idx < end) {
        int2 c = g_csr[idx];
        acc_half4(acc, tp[c.x * 32 + lane], __int_as_float(c.y));
    }

    if (FINAL) {
        acc.x = fmaxf(acc.x, 0.f); acc.y = fmaxf(acc.y, 0.f);
        acc.z = fmaxf(acc.z, 0.f); acc.w = fmaxf(acc.w, 0.f);
        int g = batch[d];
        float* p = &out[g * DD + lane * 4];
        asm volatile("red.global.add.v4.f32 [%0], {%1, %2, %3, %4};"
                     :: "l"(p), "f"(acc.x), "f"(acc.y), "f"(acc.z), "f"(acc.w)
                     : "memory");
    } else {
        ((float4*)g_h)[d * 32 + lane] = acc;
    }
}

__global__ void k_pool_div(float* __restrict__ out) {
    int i = blockIdx.x * blockDim.x + threadIdx.x;
    if (i < NG * DD) out[i] /= fmaxf(g_cnt[i >> 7], 1.0f);
}

// ================= launch =================
extern "C" void kernel_launch(void* const* d_in, const int* in_sizes, int n_in,
                              void* d_out, int out_size) {
    const float* x = (const float*)d_in[0];
    const int* ei = (const int*)d_in[1];      // int32 (JAX x64 disabled)
    const int* batch = (const int*)d_in[2];
    const float* W0 = (const float*)d_in[3];
    const float* b0 = (const float*)d_in[4];
    const float* W1 = (const float*)d_in[5];
    const float* b1 = (const float*)d_in[6];
    const float* W2 = (const float*)d_in[7];
    const float* b2 = (const float*)d_in[8];
    float* out = (float*)d_out;

    __half* tmp; cudaGetSymbolAddress((void**)&tmp, g_tmph);
    float* h;    cudaGetSymbolAddress((void**)&h, g_h);

    const int TB = 256;
    int nodeB = (NN + TB - 1) / TB;
    int edgeB = (EE + TB - 1) / TB;
    int gemmB = (NN + 63) / 64;
    int aggB = (NN * 32 + TB - 1) / TB;

    cudaStream_t s2;
    cudaStreamCreateWithFlags(&s2, cudaStreamNonBlocking);
    cudaEvent_t evFork, evJoin;
    cudaEventCreateWithFlags(&evFork, cudaEventDisableTiming);
    cudaEventCreateWithFlags(&evJoin, cudaEventDisableTiming);

    cudaEventRecord(evFork, 0);
    cudaStreamWaitEvent(s2, evFork, 0);
    k_gemm<<<gemmB, 128, 0, s2>>>(x, W0, tmp, NN, 0);
    cudaEventRecord(evJoin, s2);

    // ---- graph preprocessing on default stream ----
    k_zero<<<nodeB, TB>>>(out);
    k_deg_count<<<edgeB, TB>>>(ei);
    k_scan1<<<NCHUNK, SCAN_CHUNK>>>();
    k_scan3<<<nodeB, TB>>>(batch);
    k_csr_fill<<<edgeB, TB>>>(ei);

    cudaStreamWaitEvent(0, evJoin, 0);

    // ---- layer 0 aggregation ----
    k_agg<0><<<aggB, TB>>>(b0, batch, out);
    // ---- layer 1 ----
    k_gemm<<<gemmB, 128>>>(h, W1, tmp, NN, 1);
    k_agg<0><<<aggB, TB>>>(b1, batch, out);
    // ---- layer 2 (fused relu + pool) ----
    k_gemm<<<gemmB, 128>>>(h, W2, tmp, NN, 1);
    k_agg<1><<<aggB, TB>>>(b2, batch, out);

    k_pool_div<<<(NG * DD + TB - 1) / TB, TB>>>(out);
}

// round 14
// speedup vs baseline: 1.1031x; 1.1031x over previous
#include <cuda_runtime.h>
#include <cuda_bf16.h>
#include <cstdint>

#define NN 50000
#define EE 800000
#define DD 128
#define NG 64
#define SCAN_CHUNK 1024
#define NCHUNK ((NN + SCAN_CHUNK - 1) / SCAN_CHUNK)   // 49
#define HALF_ROWS 25024                                // 391 tiles of 64
#define GEMM_HALF_BLOCKS 391

// -------- scratch (device globals: no allocation allowed) --------
__device__ __align__(16) float g_tmpA[NN * DD];  // h @ W result (layers 0, 2)
__device__ __align__(16) float g_tmpB[NN * DD];  // h @ W result (layer 1)
__device__ __align__(16) float g_h[NN * DD];     // aggregated layer output
__device__ __align__(16) float g_dinv[NN];       // rsqrt(degree)
__device__ __align__(16) float g_cnt[NG];        // pool counts
__device__ __align__(16) int   g_degi[NN];       // int in-degree (no self loop)
__device__ __align__(16) int   g_rowptr[NN + 1]; // CSR row pointers (by dst)
__device__ __align__(16) int   g_cursor[NN];     // scatter cursors
__device__ __align__(16) int2  g_csr[EE];        // {src, norm-as-int}
__device__ __align__(16) int   g_bsum[NCHUNK];   // per-chunk totals (from scan1)

// ================= prep =================
__global__ void k_zero(float* __restrict__ out) {
    int i = blockIdx.x * blockDim.x + threadIdx.x;
    if (i < NN) g_degi[i] = 0;
    if (i < NG * DD) out[i] = 0.f;
}

__global__ void k_deg_count(const int* __restrict__ ei) {
    int e = blockIdx.x * blockDim.x + threadIdx.x;
    if (e < EE) atomicAdd(&g_degi[ei[EE + e]], 1);
}

// ---- scan phase 1 ----
__global__ void k_scan1() {
    __shared__ int wsum[32];
    int tid = threadIdx.x, lane = tid & 31, wd = tid >> 5;
    int i = blockIdx.x * SCAN_CHUNK + tid;
    int v = (i < NN) ? g_degi[i] : 0;
    int x = v;
#pragma unroll
    for (int o = 1; o < 32; o <<= 1) {
        int y = __shfl_up_sync(0xffffffffu, x, o);
        if (lane >= o) x += y;
    }
    if (lane == 31) wsum[wd] = x;
    __syncthreads();
    if (wd == 0) {
        int s = wsum[lane];
#pragma unroll
        for (int o = 1; o < 32; o <<= 1) {
            int y = __shfl_up_sync(0xffffffffu, s, o);
            if (lane >= o) s += y;
        }
        wsum[lane] = s;
    }
    __syncthreads();
    int excl = (wd ? wsum[wd - 1] : 0) + x - v;
    if (i < NN) g_rowptr[i] = excl;
    if (tid == SCAN_CHUNK - 1) g_bsum[blockIdx.x] = wsum[31];
}

// ---- scan phase 2+3 fused + pool counts (sorted batch) ----
__global__ void k_scan3(const int* __restrict__ batch) {
    __shared__ int pref[NCHUNK];
    int tid = threadIdx.x;
    if (tid == 0) {
        int run = 0;
#pragma unroll 1
        for (int j = 0; j < NCHUNK; j++) {
            int t = g_bsum[j];
            pref[j] = run;
            run += t;
        }
    }
    __syncthreads();
    int i = blockIdx.x * blockDim.x + tid;
    if (i < NN) {
        int rp = g_rowptr[i] + pref[i / SCAN_CHUNK];
        g_rowptr[i] = rp;
        g_cursor[i] = rp;
        g_dinv[i] = rsqrtf((float)(g_degi[i] + 1));
    }
    if (i == 0) g_rowptr[NN] = EE;
    if (blockIdx.x == 0 && tid < NG) {
        int g = tid;
        int lo = 0, hi = NN;
        while (lo < hi) { int m = (lo + hi) >> 1; if (batch[m] < g) lo = m + 1; else hi = m; }
        int start = lo;
        lo = 0; hi = NN;
        while (lo < hi) { int m = (lo + hi) >> 1; if (batch[m] <= g) lo = m + 1; else hi = m; }
        g_cnt[g] = (float)(lo - start);
    }
}

// ---- CSR fill: one 8B write per edge ----
__global__ void k_csr_fill(const int* __restrict__ ei) {
    int e = blockIdx.x * blockDim.x + threadIdx.x;
    if (e < EE) {
        int s = ei[e];
        int d = ei[EE + e];
        int pos = atomicAdd(&g_cursor[d], 1);
        float nm = g_dinv[s] * g_dinv[d];
        g_csr[pos] = make_int2(s, __float_as_int(nm));
    }
}

// ================= GEMM: C[rows,128] = reluOpt(A)[rows,128] @ W[128,128] =================
// operates on rows [row_base, row_base + 64*gridDim.x) clamped to NN
__global__ __launch_bounds__(128, 4)
void k_gemm(const float* __restrict__ A, const float* __restrict__ W,
            float* __restrict__ C, int relu_in, int row_base) {
    __shared__ float As[2][16][68];
    __shared__ float Ws[2][16][128];

    int tid = threadIdx.x;
    int tx = tid & 15;
    int ty = tid >> 4;
    int row0 = row_base + blockIdx.x * 64;

    unsigned long long acc[8][4];
#pragma unroll
    for (int i = 0; i < 8; i++)
#pragma unroll
        for (int j = 0; j < 4; j++) acc[i][j] = 0ull;

    float4 aR[2];
    float4 wR[4];

    auto loadT = [&](int kt) {
#pragma unroll
        for (int q = 0; q < 2; q++) {
            int id = tid + q * 128;
            int r = id >> 2;
            int kc = (id & 3) * 4;
            int grow = row0 + r;
            float4 v = make_float4(0.f, 0.f, 0.f, 0.f);
            if (grow < NN) v = *(const float4*)&A[(size_t)grow * DD + kt * 16 + kc];
            if (relu_in) {
                v.x = fmaxf(v.x, 0.f); v.y = fmaxf(v.y, 0.f);
                v.z = fmaxf(v.z, 0.f); v.w = fmaxf(v.w, 0.f);
            }
            aR[q] = v;
        }
#pragma unroll
        for (int q = 0; q < 4; q++) {
            int id = tid + q * 128;
            wR[q] = ((const float4*)&W[kt * 16 * DD])[id];
        }
    };
    auto stsT = [&](int b) {
#pragma unroll
        for (int q = 0; q < 2; q++) {
            int id = tid + q * 128;
            int r = id >> 2;
            int kc = (id & 3) * 4;
            As[b][kc + 0][r] = aR[q].x;
            As[b][kc + 1][r] = aR[q].y;
            As[b][kc + 2][r] = aR[q].z;
            As[b][kc + 3][r] = aR[q].w;
        }
#pragma unroll
        for (int q = 0; q < 4; q++) {
            int id = tid + q * 128;
            ((float4*)Ws[b])[id] = wR[q];
        }
    };

    loadT(0);
    stsT(0);
    __syncthreads();

    for (int kt = 0; kt < 8; kt++) {
        if (kt < 7) loadT(kt + 1);
        int b = kt & 1;
#pragma unroll
        for (int k = 0; k < 16; k++) {
            float4 a0 = *(float4*)&As[b][k][ty * 8];
            float4 a1 = *(float4*)&As[b][k][ty * 8 + 4];
            ulonglong2 w0 = *(ulonglong2*)&Ws[b][k][tx * 8];
            ulonglong2 w1 = *(ulonglong2*)&Ws[b][k][tx * 8 + 4];
            unsigned long long wp[4] = {w0.x, w0.y, w1.x, w1.y};
            float av[8] = {a0.x, a0.y, a0.z, a0.w, a1.x, a1.y, a1.z, a1.w};
#pragma unroll
            for (int i = 0; i < 8; i++) {
                unsigned long long ap;
                asm("mov.b64 %0, {%1, %1};" : "=l"(ap) : "r"(__float_as_uint(av[i])));
#pragma unroll
                for (int j = 0; j < 4; j++) {
                    asm("fma.rn.f32x2 %0, %1, %2, %0;"
                        : "+l"(acc[i][j]) : "l"(ap), "l"(wp[j]));
                }
            }
        }
        if (kt < 7) {
            stsT((kt + 1) & 1);
            __syncthreads();
        }
    }

#pragma unroll
    for (int i = 0; i < 8; i++) {
        int grow = row0 + ty * 8 + i;
        if (grow < NN) {
            float o[8];
#pragma unroll
            for (int j = 0; j < 4; j++) {
                unsigned int lo, hi;
                asm("mov.b64 {%0, %1}, %2;" : "=r"(lo), "=r"(hi) : "l"(acc[i][j]));
                o[2 * j] = __uint_as_float(lo);
                o[2 * j + 1] = __uint_as_float(hi);
            }
            *(float4*)&C[(size_t)grow * DD + tx * 8] = make_float4(o[0], o[1], o[2], o[3]);
            *(float4*)&C[(size_t)grow * DD + tx * 8 + 4] = make_float4(o[4], o[5], o[6], o[7]);
        }
    }
}

// ================= gather aggregation: one warp per dst node in [node_base, node_end) =================
template <int FINAL>
__global__ void k_agg(const float* __restrict__ tmp,
                      const float* __restrict__ b,
                      const int* __restrict__ batch,
                      float* __restrict__ out,
                      int node_base, int node_end) {
    int warp = (blockIdx.x * blockDim.x + threadIdx.x) >> 5;
    int lane = threadIdx.x & 31;
    int d = node_base + warp;
    if (d >= node_end) return;

    float di = g_dinv[d];
    float n2 = di * di;
    float4 bb = ((const float4*)b)[lane];
    float4 v = ((const float4*)tmp)[d * 32 + lane];
    float4 acc;
    acc.x = fmaf(v.x, n2, bb.x); acc.y = fmaf(v.y, n2, bb.y);
    acc.z = fmaf(v.z, n2, bb.z); acc.w = fmaf(v.w, n2, bb.w);

    int idx = g_rowptr[d];
    int end = g_rowptr[d + 1];
    for (; idx + 1 < end; idx += 2) {
        int2 c0 = g_csr[idx];
        int2 c1 = g_csr[idx + 1];
        float n0 = __int_as_float(c0.y);
        float n1 = __int_as_float(c1.y);
        float4 u0 = ((const float4*)tmp)[c0.x * 32 + lane];
        float4 u1 = ((const float4*)tmp)[c1.x * 32 + lane];
        acc.x = fmaf(u0.x, n0, acc.x); acc.y = fmaf(u0.y, n0, acc.y);
        acc.z = fmaf(u0.z, n0, acc.z); acc.w = fmaf(u0.w, n0, acc.w);
        acc.x = fmaf(u1.x, n1, acc.x); acc.y = fmaf(u1.y, n1, acc.y);
        acc.z = fmaf(u1.z, n1, acc.z); acc.w = fmaf(u1.w, n1, acc.w);
    }
    if (idx < end) {
        int2 c = g_csr[idx];
        float nm = __int_as_float(c.y);
        float4 u = ((const float4*)tmp)[c.x * 32 + lane];
        acc.x = fmaf(u.x, nm, acc.x); acc.y = fmaf(u.y, nm, acc.y);
        acc.z = fmaf(u.z, nm, acc.z); acc.w = fmaf(u.w, nm, acc.w);
    }

    if (FINAL) {
        acc.x = fmaxf(acc.x, 0.f); acc.y = fmaxf(acc.y, 0.f);
        acc.z = fmaxf(acc.z, 0.f); acc.w = fmaxf(acc.w, 0.f);
        int g = batch[d];
        float* p = &out[g * DD + lane * 4];
        asm volatile("red.global.add.v4.f32 [%0], {%1, %2, %3, %4};"
                     :: "l"(p), "f"(acc.x), "f"(acc.y), "f"(acc.z), "f"(acc.w)
                     : "memory");
    } else {
        ((float4*)g_h)[d * 32 + lane] = acc;
    }
}

__global__ void k_pool_div(float* __restrict__ out) {
    int i = blockIdx.x * blockDim.x + threadIdx.x;
    if (i < NG * DD) out[i] /= fmaxf(g_cnt[i >> 7], 1.0f);
}

// ================= launch =================
extern "C" void kernel_launch(void* const* d_in, const int* in_sizes, int n_in,
                              void* d_out, int out_size) {
    const float* x = (const float*)d_in[0];
    const int* ei = (const int*)d_in[1];      // int32 (JAX x64 disabled)
    const int* batch = (const int*)d_in[2];
    const float* W0 = (const float*)d_in[3];
    const float* b0 = (const float*)d_in[4];
    const float* W1 = (const float*)d_in[5];
    const float* b1 = (const float*)d_in[6];
    const float* W2 = (const float*)d_in[7];
    const float* b2 = (const float*)d_in[8];
    float* out = (float*)d_out;

    float* tmpA; cudaGetSymbolAddress((void**)&tmpA, g_tmpA);
    float* tmpB; cudaGetSymbolAddress((void**)&tmpB, g_tmpB);
    float* h;    cudaGetSymbolAddress((void**)&h, g_h);

    const int TB = 256;
    int nodeB = (NN + TB - 1) / TB;
    int edgeB = (EE + TB - 1) / TB;
    // agg half grids (warp per node)
    int aggA_B = (HALF_ROWS * 32 + TB - 1) / TB;
    int aggB_B = ((NN - HALF_ROWS) * 32 + TB - 1) / TB;
    int aggFull_B = (NN * 32 + TB - 1) / TB;

    cudaStream_t s2;
    cudaStreamCreateWithFlags(&s2, cudaStreamNonBlocking);
    cudaEvent_t evFork, evG0, evA0A, evA0B, evG1B, evA1A, evA1B, evG2B;
    cudaEventCreateWithFlags(&evFork, cudaEventDisableTiming);
    cudaEventCreateWithFlags(&evG0, cudaEventDisableTiming);
    cudaEventCreateWithFlags(&evA0A, cudaEventDisableTiming);
    cudaEventCreateWithFlags(&evA0B, cudaEventDisableTiming);
    cudaEventCreateWithFlags(&evG1B, cudaEventDisableTiming);
    cudaEventCreateWithFlags(&evA1A, cudaEventDisableTiming);
    cudaEventCreateWithFlags(&evA1B, cudaEventDisableTiming);
    cudaEventCreateWithFlags(&evG2B, cudaEventDisableTiming);

    // ---- fork: gemm0 on s2 concurrent with graph prep on s0 ----
    cudaEventRecord(evFork, 0);
    cudaStreamWaitEvent(s2, evFork, 0);
    k_gemm<<<2 * GEMM_HALF_BLOCKS, 128, 0, s2>>>(x, W0, tmpA, 0, 0);
    cudaEventRecord(evG0, s2);

    k_zero<<<nodeB, TB>>>(out);
    k_deg_count<<<edgeB, TB>>>(ei);
    k_scan1<<<NCHUNK, SCAN_CHUNK>>>();
    k_scan3<<<nodeB, TB>>>(batch);
    k_csr_fill<<<edgeB, TB>>>(ei);

    cudaStreamWaitEvent(0, evG0, 0);

    // ---- layer 0 aggregation, split halves; gemm1 halves chase on s2 ----
    k_agg<0><<<aggA_B, TB>>>(tmpA, b0, batch, out, 0, HALF_ROWS);
    cudaEventRecord(evA0A, 0);
    k_agg<0><<<aggB_B, TB>>>(tmpA, b0, batch, out, HALF_ROWS, NN);
    cudaEventRecord(evA0B, 0);

    cudaStreamWaitEvent(s2, evA0A, 0);
    k_gemm<<<GEMM_HALF_BLOCKS, 128, 0, s2>>>(h, W1, tmpB, 1, 0);
    cudaStreamWaitEvent(s2, evA0B, 0);
    k_gemm<<<GEMM_HALF_BLOCKS, 128, 0, s2>>>(h, W1, tmpB, 1, HALF_ROWS);
    cudaEventRecord(evG1B, s2);

    // ---- layer 1 aggregation (needs all of gemm1); gemm2 halves chase ----
    cudaStreamWaitEvent(0, evG1B, 0);
    k_agg<0><<<aggA_B, TB>>>(tmpB, b1, batch, out, 0, HALF_ROWS);
    cudaEventRecord(evA1A, 0);
    k_agg<0><<<aggB_B, TB>>>(tmpB, b1, batch, out, HALF_ROWS, NN);
    cudaEventRecord(evA1B, 0);

    cudaStreamWaitEvent(s2, evA1A, 0);
    k_gemm<<<GEMM_HALF_BLOCKS, 128, 0, s2>>>(h, W2, tmpA, 1, 0);
    cudaStreamWaitEvent(s2, evA1B, 0);
    k_gemm<<<GEMM_HALF_BLOCKS, 128, 0, s2>>>(h, W2, tmpA, 1, HALF_ROWS);
    cudaEventRecord(evG2B, s2);

    // ---- layer 2: fused relu + pool (needs all of gemm2) ----
    cudaStreamWaitEvent(0, evG2B, 0);
    k_agg<1><<<aggFull_B, TB>>>(tmpA, b2, batch, out, 0, NN);

    k_pool_div<<<(NG * DD + TB - 1) / TB, TB>>>(out);
}